// round 1
// baseline (speedup 1.0000x reference)
#include <cuda_runtime.h>
#include <cuda_bf16.h>

// Problem: y[m] = 0.75 * sum_k( x[m,k] * wcs[k] ), wcs[k] = sum_n weight[n,k]
// x: [M,K] fp32, weight: [N,K] fp32, out: [M,1] fp32
// M = K = N = 8192. Pure HBM-streaming problem (512 MiB compulsory traffic).

#define MM 8192
#define KK 8192
#define NN 8192

__device__ float g_wcs[KK];  // column-sum scratch (device global: no allocs)

// ---------------------------------------------------------------- zero wcs
__global__ void zero_wcs_kernel() {
    int i = blockIdx.x * blockDim.x + threadIdx.x;
    if (i < KK) g_wcs[i] = 0.0f;
}

// ------------------------------------------------- column sum of weight[N,K]
// Grid: x = column tiles (K/1024), y = row chunks. Block: 256 threads.
// Each thread owns one float4 column-group, accumulates ROWS_PER_CHUNK rows,
// then atomically adds 4 partials into g_wcs.
#define CS_THREADS 256
#define ROW_CHUNKS 64
#define ROWS_PER_CHUNK (NN / ROW_CHUNKS)  // 128

__global__ __launch_bounds__(CS_THREADS) void colsum_kernel(const float* __restrict__ weight) {
    const int col4 = blockIdx.x * CS_THREADS + threadIdx.x;   // float4 index into a row
    const int row0 = blockIdx.y * ROWS_PER_CHUNK;

    const float4* __restrict__ w4 = reinterpret_cast<const float4*>(weight);
    const int row_stride4 = KK / 4;  // 2048 float4 per row

    float4 acc = make_float4(0.f, 0.f, 0.f, 0.f);
    const float4* p = w4 + (size_t)row0 * row_stride4 + col4;

#pragma unroll 8
    for (int r = 0; r < ROWS_PER_CHUNK; ++r) {
        float4 v = p[(size_t)r * row_stride4];
        acc.x += v.x; acc.y += v.y; acc.z += v.z; acc.w += v.w;
    }

    const int col = col4 * 4;
    atomicAdd(&g_wcs[col + 0], acc.x);
    atomicAdd(&g_wcs[col + 1], acc.y);
    atomicAdd(&g_wcs[col + 2], acc.z);
    atomicAdd(&g_wcs[col + 3], acc.w);
}

// ------------------------------------------------- per-row dot with g_wcs
// One block (256 threads) per output row. Each thread handles 8 float4 groups.
#define DOT_THREADS 256

__global__ __launch_bounds__(DOT_THREADS) void rowdot_kernel(const float* __restrict__ x,
                                                             float* __restrict__ out) {
    const int row = blockIdx.x;
    const float4* __restrict__ x4 = reinterpret_cast<const float4*>(x) + (size_t)row * (KK / 4);
    const float4* __restrict__ w4 = reinterpret_cast<const float4*>(g_wcs);

    float acc = 0.0f;
#pragma unroll
    for (int i = 0; i < (KK / 4) / DOT_THREADS; ++i) {   // 8 iterations
        const int idx = i * DOT_THREADS + threadIdx.x;
        float4 xv = x4[idx];
        float4 wv = w4[idx];
        acc = fmaf(xv.x, wv.x, acc);
        acc = fmaf(xv.y, wv.y, acc);
        acc = fmaf(xv.z, wv.z, acc);
        acc = fmaf(xv.w, wv.w, acc);
    }

    // warp reduce
#pragma unroll
    for (int off = 16; off > 0; off >>= 1)
        acc += __shfl_down_sync(0xFFFFFFFFu, acc, off);

    __shared__ float warp_sums[DOT_THREADS / 32];
    const int lane = threadIdx.x & 31;
    const int wid  = threadIdx.x >> 5;
    if (lane == 0) warp_sums[wid] = acc;
    __syncthreads();

    if (wid == 0) {
        float s = (lane < DOT_THREADS / 32) ? warp_sums[lane] : 0.0f;
#pragma unroll
        for (int off = 4; off > 0; off >>= 1)
            s += __shfl_down_sync(0xFFFFFFFFu, s, off);
        if (lane == 0) out[row] = 0.75f * s;
    }
}

// ---------------------------------------------------------------- launcher
extern "C" void kernel_launch(void* const* d_in, const int* in_sizes, int n_in,
                              void* d_out, int out_size) {
    const float* x      = (const float*)d_in[0];
    const float* weight = (const float*)d_in[1];
    float* out = (float*)d_out;

    zero_wcs_kernel<<<(KK + 255) / 256, 256>>>();

    dim3 cs_grid(KK / (CS_THREADS * 4), ROW_CHUNKS);  // (8, 64)
    colsum_kernel<<<cs_grid, CS_THREADS>>>(weight);

    rowdot_kernel<<<MM, DOT_THREADS>>>(x, out);
}